// round 10
// baseline (speedup 1.0000x reference)
#include <cuda_runtime.h>
#include <cuda_bf16.h>
#include <math.h>
#include <stdint.h>

#define B 256
#define DIM 1024
#define H 8
#define D 128
#define P 2048
#define HD 1024
#define KER 4

// ---------------- scratch (static device memory; no allocs) ----------------
__device__ float g_xn[B * DIM];
__device__ float g_xt[B * P];
__device__ float g_xc[B * P];
__device__ float g_rt[B * HD];
__device__ float g_q[B * HD];
__device__ float g_k[B * HD];
__device__ float g_v[B * HD];
__device__ float g_o[B * HD];
__device__ float g_sk[B * HD];
__device__ float g_ie[B * H];
__device__ float g_fe[B * H];
__device__ float g_y[B * HD];
#define SEG (B * HD)
__device__ float g_p0[6 * SEG];
__device__ float g_p1[6 * SEG];

__device__ __forceinline__ uint32_t smem_u32(const void* p) {
    uint32_t a;
    asm("{ .reg .u64 t; cvta.to.shared.u64 t, %1; cvt.u32.u64 %0, t; }" : "=r"(a) : "l"(p));
    return a;
}

#define LDM4(r, a) \
    asm volatile("ldmatrix.sync.aligned.m8n8.x4.shared.b16 {%0,%1,%2,%3}, [%4];" \
        : "=r"((r)[0]), "=r"((r)[1]), "=r"((r)[2]), "=r"((r)[3]) : "r"(a))

#define MMA(d, a, b0, b1) \
    asm volatile("mma.sync.aligned.m16n8k16.row.col.f32.bf16.bf16.f32 " \
        "{%0,%1,%2,%3}, {%4,%5,%6,%7}, {%8,%9}, {%0,%1,%2,%3};" \
        : "+f"((d)[0]), "+f"((d)[1]), "+f"((d)[2]), "+f"((d)[3]) \
        : "r"((a)[0]), "r"((a)[1]), "r"((a)[2]), "r"((a)[3]), "r"(b0), "r"(b1))

// ================= layernorm =================
__global__ void ln_kernel(const float* __restrict__ x, const float* __restrict__ g,
                          const float* __restrict__ bta, float* __restrict__ out) {
    int row = blockIdx.x;
    int tid = threadIdx.x;
    const float4* xr = (const float4*)(x + (size_t)row * DIM);
    float4 v = xr[tid];
    float s  = v.x + v.y + v.z + v.w;
    float ss = v.x * v.x + v.y * v.y + v.z * v.z + v.w * v.w;
    __shared__ float shs[8], shss[8];
    __shared__ float mu_s, rstd_s;
    #pragma unroll
    for (int o = 16; o; o >>= 1) {
        s  += __shfl_down_sync(0xffffffffu, s, o);
        ss += __shfl_down_sync(0xffffffffu, ss, o);
    }
    int w = tid >> 5, lane = tid & 31;
    if (lane == 0) { shs[w] = s; shss[w] = ss; }
    __syncthreads();
    if (tid == 0) {
        float ts = 0.f, tss = 0.f;
        #pragma unroll
        for (int i = 0; i < 8; i++) { ts += shs[i]; tss += shss[i]; }
        float mu = ts * (1.f / DIM);
        float var = tss * (1.f / DIM) - mu * mu;
        mu_s = mu;
        rstd_s = rsqrtf(var + 1e-5f);
    }
    __syncthreads();
    float mu = mu_s, rs = rstd_s;
    float4 g4 = ((const float4*)g)[tid];
    float4 b4 = ((const float4*)bta)[tid];
    float4 r;
    r.x = (v.x - mu) * rs * g4.x + b4.x;
    r.y = (v.y - mu) * rs * g4.y + b4.y;
    r.z = (v.z - mu) * rs * g4.z + b4.z;
    r.w = (v.w - mu) * rs * g4.w + b4.w;
    ((float4*)(out + (size_t)row * DIM))[tid] = r;
}

// ================= tensor-core GEMM NT via mma.sync =======
// C[M,N] = A[M,K] @ W[N,K]^T, fp32 in/out, bf16 hi/lo split (3 MMA terms)
struct GemmDesc {
    const float* A;      // pre-offset by k0
    const float* W;      // pre-offset by k0
    const float* bias;   // nullable
    const float* res;    // nullable
    float* C;
    int N;
    int ldk;
    int kn;
    int epi;             // 0 none, 1 sigmoid
};
struct GemmArgs { GemmDesc d[10]; };

// global -> regs: TM rows x 32 fp32; thread handles (row, 8-float granule)
template<int CNT2, int NTHR>
__device__ __forceinline__ void ldg_rows2(const float* __restrict__ g, int ldk, int k0,
                                          float4 (&p)[CNT2 * 2], int tid) {
    #pragma unroll
    for (int i = 0; i < CNT2; i++) {
        int idx = tid + i * NTHR;
        int r = idx >> 2, g8 = idx & 3;
        const float* src = g + (size_t)r * ldk + k0 + g8 * 8;
        p[2 * i]     = *(const float4*)(src);
        p[2 * i + 1] = *(const float4*)(src + 4);
    }
}
// regs -> bf16 hi/lo -> padded SMEM (80B row stride), STS.128 per plane
template<int CNT2, int NTHR>
__device__ __forceinline__ void cvt_sts2(const float4 (&p)[CNT2 * 2], char* hi, char* lo,
                                         int tid) {
    #pragma unroll
    for (int i = 0; i < CNT2; i++) {
        int idx = tid + i * NTHR;
        int r = idx >> 2, g8 = idx & 3;
        float4 v0 = p[2 * i], v1 = p[2 * i + 1];
        uint32_t a0 = __float_as_uint(v0.x), a1 = __float_as_uint(v0.y);
        uint32_t a2 = __float_as_uint(v0.z), a3 = __float_as_uint(v0.w);
        uint32_t b0 = __float_as_uint(v1.x), b1 = __float_as_uint(v1.y);
        uint32_t b2 = __float_as_uint(v1.z), b3 = __float_as_uint(v1.w);
        uint4 hv;
        hv.x = __byte_perm(a0, a1, 0x7632);
        hv.y = __byte_perm(a2, a3, 0x7632);
        hv.z = __byte_perm(b0, b1, 0x7632);
        hv.w = __byte_perm(b2, b3, 0x7632);
        float r0 = v0.x - __uint_as_float(a0 & 0xffff0000u);
        float r1 = v0.y - __uint_as_float(a1 & 0xffff0000u);
        float r2 = v0.z - __uint_as_float(a2 & 0xffff0000u);
        float r3 = v0.w - __uint_as_float(a3 & 0xffff0000u);
        float r4 = v1.x - __uint_as_float(b0 & 0xffff0000u);
        float r5 = v1.y - __uint_as_float(b1 & 0xffff0000u);
        float r6 = v1.z - __uint_as_float(b2 & 0xffff0000u);
        float r7 = v1.w - __uint_as_float(b3 & 0xffff0000u);
        uint4 lv;
        asm("cvt.rn.bf16x2.f32 %0, %1, %2;" : "=r"(lv.x) : "f"(r1), "f"(r0));
        asm("cvt.rn.bf16x2.f32 %0, %1, %2;" : "=r"(lv.y) : "f"(r3), "f"(r2));
        asm("cvt.rn.bf16x2.f32 %0, %1, %2;" : "=r"(lv.z) : "f"(r5), "f"(r4));
        asm("cvt.rn.bf16x2.f32 %0, %1, %2;" : "=r"(lv.w) : "f"(r7), "f"(r6));
        int off = r * 80 + g8 * 16;
        *(uint4*)(hi + off) = hv;
        *(uint4*)(lo + off) = lv;
    }
}

template<int TM, int TN, int NTHR>
__global__ __launch_bounds__(NTHR, (NTHR == 128) ? ((TM == 128) ? 2 : 3) : 1)
void gemm_mma(GemmArgs args) {
    extern __shared__ char smem[];
    constexpr int MATA = TM * 80;
    constexpr int MATW = TN * 80;
    constexpr int STG = 2 * (MATA + MATW);
    constexpr int CA2 = TM * 4 / NTHR;
    constexpr int CW2 = TN * 4 / NTHR;
    constexpr int MW = TM / 32;              // warps along M
    constexpr int NWZ = (NTHR / 32) / MW;    // warps along N
    constexpr int WN = TN / NWZ;             // warp tile N width
    constexpr int NI = WN / 8;               // n8 fragments per warp
    constexpr int BLD = WN / 16;             // B LDM4s per plane per ks

    const GemmDesc dd = args.d[blockIdx.z];
    const int N = dd.N, ldk = dd.ldk;
    const int bn0 = blockIdx.x * TN;
    const int bm0 = blockIdx.y * TM;
    if (bn0 >= N) return;

    const int tid = threadIdx.x;
    const int wid = tid >> 5, lane = tid & 31;
    const int m0 = (wid % MW) * 32;
    const int n0 = (wid / MW) * WN;
    const int grp = lane >> 3, lrow = lane & 7;
    const uint32_t sbase = smem_u32(smem);

    const float* Ag = dd.A + (size_t)bm0 * ldk;
    const float* Wg = dd.W + (size_t)bn0 * ldk;

    uint32_t aoff[2], boff[BLD];
    #pragma unroll
    for (int mi = 0; mi < 2; mi++)
        aoff[mi] = (uint32_t)((m0 + mi * 16 + (grp & 1) * 8 + lrow) * 80 + (grp >> 1) * 16);
    #pragma unroll
    for (int bi = 0; bi < BLD; bi++)
        boff[bi] = (uint32_t)((n0 + bi * 16 + (grp >> 1) * 8 + lrow) * 80 + (grp & 1) * 16);

    float acc[2][NI][4];
    #pragma unroll
    for (int mi = 0; mi < 2; mi++)
        #pragma unroll
        for (int ni = 0; ni < NI; ni++)
            acc[mi][ni][0] = acc[mi][ni][1] = acc[mi][ni][2] = acc[mi][ni][3] = 0.f;

    const int nk = dd.kn;
    // prologue: fill stage 0
    {
        float4 pA[CA2 * 2], pW[CW2 * 2];
        ldg_rows2<CA2, NTHR>(Ag, ldk, 0, pA, tid);
        ldg_rows2<CW2, NTHR>(Wg, ldk, 0, pW, tid);
        cvt_sts2<CA2, NTHR>(pA, smem, smem + MATA, tid);
        cvt_sts2<CW2, NTHR>(pW, smem + 2 * MATA, smem + 2 * MATA + MATW, tid);
    }
    __syncthreads();

    for (int it = 0; it < nk; it++) {
        float4 pA[CA2 * 2], pW[CW2 * 2];
        if (it + 1 < nk) {
            ldg_rows2<CA2, NTHR>(Ag, ldk, (it + 1) << 5, pA, tid);
            ldg_rows2<CW2, NTHR>(Wg, ldk, (it + 1) << 5, pW, tid);
        }
        const uint32_t sA  = sbase + (it & 1) * STG;
        const uint32_t sAl = sA + MATA, sWh = sA + 2 * MATA, sWl = sA + 2 * MATA + MATW;
        #pragma unroll
        for (int ks = 0; ks < 2; ks++) {
            const uint32_t kb = ks * 32;
            uint32_t Ah[2][4], Al[2][4], Bh[NI][2], Bl[NI][2];
            #pragma unroll
            for (int mi = 0; mi < 2; mi++) {
                LDM4(Ah[mi], sA  + aoff[mi] + kb);
                LDM4(Al[mi], sAl + aoff[mi] + kb);
            }
            #pragma unroll
            for (int bi = 0; bi < BLD; bi++) {
                uint32_t t[4];
                LDM4(t, sWh + boff[bi] + kb);
                Bh[2 * bi][0] = t[0]; Bh[2 * bi][1] = t[1];
                Bh[2 * bi + 1][0] = t[2]; Bh[2 * bi + 1][1] = t[3];
                LDM4(t, sWl + boff[bi] + kb);
                Bl[2 * bi][0] = t[0]; Bl[2 * bi][1] = t[1];
                Bl[2 * bi + 1][0] = t[2]; Bl[2 * bi + 1][1] = t[3];
            }
            #pragma unroll
            for (int mi = 0; mi < 2; mi++)
                #pragma unroll
                for (int ni = 0; ni < NI; ni++) {
                    MMA(acc[mi][ni], Ah[mi], Bh[ni][0], Bh[ni][1]);
                    MMA(acc[mi][ni], Ah[mi], Bl[ni][0], Bl[ni][1]);
                    MMA(acc[mi][ni], Al[mi], Bh[ni][0], Bh[ni][1]);
                }
        }
        if (it + 1 < nk) {
            char* st = smem + ((it + 1) & 1) * STG;
            cvt_sts2<CA2, NTHR>(pA, st, st + MATA, tid);
            cvt_sts2<CW2, NTHR>(pW, st + 2 * MATA, st + 2 * MATA + MATW, tid);
        }
        __syncthreads();
    }

    // epilogue
    const int qrow = lane >> 2, qcol = (lane & 3) * 2;
    #pragma unroll
    for (int ni = 0; ni < NI; ni++) {
        const int c = bn0 + n0 + ni * 8 + qcol;
        float2 bb = make_float2(0.f, 0.f);
        if (dd.bias) bb = *(const float2*)(dd.bias + c);
        #pragma unroll
        for (int mi = 0; mi < 2; mi++) {
            const int r = bm0 + m0 + mi * 16 + qrow;
            float v0 = acc[mi][ni][0] + bb.x;
            float v1 = acc[mi][ni][1] + bb.y;
            float v2 = acc[mi][ni][2] + bb.x;
            float v3 = acc[mi][ni][3] + bb.y;
            if (dd.epi == 1) {
                v0 = 1.f / (1.f + expf(-v0)); v1 = 1.f / (1.f + expf(-v1));
                v2 = 1.f / (1.f + expf(-v2)); v3 = 1.f / (1.f + expf(-v3));
            }
            if (dd.res) {
                float2 r0 = *(const float2*)(dd.res + (size_t)r * N + c);
                float2 r1 = *(const float2*)(dd.res + (size_t)(r + 8) * N + c);
                v0 += r0.x; v1 += r0.y; v2 += r1.x; v3 += r1.y;
            }
            *(float2*)(dd.C + (size_t)r * N + c) = make_float2(v0, v1);
            *(float2*)(dd.C + (size_t)(r + 8) * N + c) = make_float2(v2, v3);
        }
    }
}

#define SMEM_A (2 * 2 * (64 * 80 + 128 * 80))   // <64,128>: 61440
#define SMEM_B (2 * 2 * (64 * 80 + 64 * 80))    // <64,64>:  40960
#define SMEM_C (2 * 2 * (128 * 80 + 64 * 80))   // <128,64>: 61440

// ================= combine: C = epi(p0 + p1 + bias) (+res) =================
struct CEnt { const float* p0; const float* p1; const float* bias;
              const float* res; float* C; int epi; };
struct CArgs { CEnt e[5]; };

__global__ __launch_bounds__(256) void combine_kernel(CArgs a) {
    CEnt e = a.e[blockIdx.z];
    int i = blockIdx.x * 256 + threadIdx.x;      // float4 index, N = 1024
    float4 x = ((const float4*)e.p0)[i];
    float4 y = ((const float4*)e.p1)[i];
    float v0 = x.x + y.x, v1 = x.y + y.y, v2 = x.z + y.z, v3 = x.w + y.w;
    if (e.bias) {
        float4 b = ((const float4*)e.bias)[i & 255];
        v0 += b.x; v1 += b.y; v2 += b.z; v3 += b.w;
    }
    if (e.epi == 1) {
        v0 = 1.f / (1.f + expf(-v0)); v1 = 1.f / (1.f + expf(-v1));
        v2 = 1.f / (1.f + expf(-v2)); v3 = 1.f / (1.f + expf(-v3));
    }
    if (e.res) {
        float4 r = ((const float4*)e.res)[i];
        v0 += r.x; v1 += r.y; v2 += r.z; v3 += r.w;
    }
    ((float4*)e.C)[i] = make_float4(v0, v1, v2, v3);
}

// ================= fused causal conv (k=4) + silu + i/f gates ================
__global__ __launch_bounds__(256) void conv_if_kernel(
        const float* __restrict__ xt, const float* __restrict__ w,
        const float* __restrict__ cb, float* __restrict__ xc,
        const float* __restrict__ Wi, const float* __restrict__ bi,
        const float* __restrict__ Wf, const float* __restrict__ bfb,
        const float* __restrict__ m_tm1, float* __restrict__ m_out,
        float* __restrict__ ie, float* __restrict__ fe) {
    __shared__ float sx[P];
    __shared__ float sc[P];
    int b = blockIdx.x;
    int tid = threadIdx.x;
    const float4* xr = (const float4*)(xt + (size_t)b * P);
    #pragma unroll
    for (int i = 0; i < P / 4 / 256; i++)
        ((float4*)sx)[tid + i * 256] = xr[tid + i * 256];
    float w0 = w[0], w1 = w[1], w2 = w[2], w3 = w[3], cbv = cb[0];
    __syncthreads();
    #pragma unroll
    for (int i = 0; i < P / 256; i++) {
        int p = tid + i * 256;
        float acc = cbv + w3 * sx[p];
        if (p >= 1) acc += w2 * sx[p - 1];
        if (p >= 2) acc += w1 * sx[p - 2];
        if (p >= 3) acc += w0 * sx[p - 3];
        float s = acc / (1.f + expf(-acc));
        sc[p] = s;
        xc[(size_t)b * P + p] = s;
    }
    __syncthreads();
    int h = tid >> 5, lane = tid & 31;
    const float* wi = Wi + (size_t)h * P;
    const float* wf = Wf + (size_t)h * P;
    float ai = 0.f, af = 0.f;
    #pragma unroll
    for (int k = lane * 4; k < P; k += 128) {
        float4 xv  = *(const float4*)(sc + k);
        float4 wiv = *(const float4*)(wi + k);
        float4 wfv = *(const float4*)(wf + k);
        ai += xv.x * wiv.x + xv.y * wiv.y + xv.z * wiv.z + xv.w * wiv.w;
        af += xv.x * wfv.x + xv.y * wfv.y + xv.z * wfv.z + xv.w * wfv.w;
    }
    #pragma unroll
    for (int o = 16; o; o >>= 1) {
        ai += __shfl_down_sync(0xffffffffu, ai, o);
        af += __shfl_down_sync(0xffffffffu, af, o);
    }
    if (lane == 0) {
        int bh = b * H + h;
        float i_t = ai + bi[h];
        float f_t = af + bfb[h];
        float mp = m_tm1[bh];
        float m = fmaxf(f_t + mp, i_t);
        m_out[bh] = m;
        ie[bh] = expf(i_t - m);
        fe[bh] = expf(f_t - m + mp);
    }
}

// ================= fused state update + readout + groupnorm + gating ========
__global__ __launch_bounds__(128) void state_kernel(
    const float* __restrict__ c_tm1, const float* __restrict__ n_tm1,
    const float* __restrict__ q, const float* __restrict__ k, const float* __restrict__ v,
    const float* __restrict__ o, const float* __restrict__ ie_, const float* __restrict__ fe_,
    const float* __restrict__ skip, const float* __restrict__ r,
    const float* __restrict__ gn_g, const float* __restrict__ gn_b,
    float* __restrict__ c_out, float* __restrict__ n_out, float* __restrict__ y) {
    int bh = blockIdx.x;
    int b = bh >> 3, h = bh & 7;
    __shared__ float qs[D], ks[D], vs[D], hnum[D];
    __shared__ float red[4], rs1[4], rs2[4];
    int tid = threadIdx.x;
    int base = b * HD + h * D;
    qs[tid] = q[base + tid];
    ks[tid] = k[base + tid] * 0.08838834764831845f;   // 1/sqrt(128)
    vs[tid] = v[base + tid];
    float ie = ie_[bh], fe = fe_[bh];
    __syncthreads();

    const float4* crow = (const float4*)(c_tm1 + (size_t)bh * D * D);
    float4* cout = (float4*)(c_out + (size_t)bh * D * D);
    int w = tid >> 5, lane = tid & 31;
    float4 k4 = ((const float4*)ks)[lane];
    float4 q4 = ((const float4*)qs)[lane];
    #pragma unroll 4
    for (int it = 0; it < 32; it++) {
        int d = it * 4 + w;
        float4 c4 = crow[d * 32 + lane];
        float ivd = ie * vs[d];
        float4 cn;
        cn.x = fe * c4.x + ivd * k4.x;
        cn.y = fe * c4.y + ivd * k4.y;
        cn.z = fe * c4.z + ivd * k4.z;
        cn.w = fe * c4.w + ivd * k4.w;
        cout[d * 32 + lane] = cn;
        float part = cn.x * q4.x + cn.y * q4.y + cn.z * q4.z + cn.w * q4.w;
        #pragma unroll
        for (int off = 16; off; off >>= 1) part += __shfl_down_sync(0xffffffffu, part, off);
        if (lane == 0) hnum[d] = part;
    }
    __syncthreads();

    int d = tid;
    float nv = fe * n_tm1[bh * D + d] + ie * ks[d];
    n_out[bh * D + d] = nv;
    float dn = nv * qs[d];
    #pragma unroll
    for (int off = 16; off; off >>= 1) dn += __shfl_down_sync(0xffffffffu, dn, off);
    if (lane == 0) red[w] = dn;
    __syncthreads();
    float denom = fmaxf(red[0] + red[1] + red[2] + red[3], 1.0f);
    float ht = o[base + d] * hnum[d] / denom;

    float s1 = ht, s2 = ht * ht;
    #pragma unroll
    for (int off = 16; off; off >>= 1) {
        s1 += __shfl_down_sync(0xffffffffu, s1, off);
        s2 += __shfl_down_sync(0xffffffffu, s2, off);
    }
    if (lane == 0) { rs1[w] = s1; rs2[w] = s2; }
    __syncthreads();
    float mu  = (rs1[0] + rs1[1] + rs1[2] + rs1[3]) * (1.f / D);
    float var = (rs2[0] + rs2[1] + rs2[2] + rs2[3]) * (1.f / D) - mu * mu;
    float rstd = rsqrtf(var + 1e-5f);
    float xn = (ht - mu) * rstd * gn_g[h * D + d] + gn_b[h * D + d];
    float rv = r[base + d];
    float yv = (xn + skip[base + d]) * (rv / (1.f + expf(-rv)));
    y[base + d] = yv;
}

// ---------------------------------------------------------------------------
extern "C" void kernel_launch(void* const* d_in, const int* in_sizes, int n_in,
                              void* d_out, int out_size) {
    const float* seq    = (const float*)d_in[0];
    const float* c_tm1  = (const float*)d_in[1];
    const float* n_tm1  = (const float*)d_in[2];
    const float* m_tm1  = (const float*)d_in[3];
    const float* ln_g   = (const float*)d_in[4];
    const float* ln_b   = (const float*)d_in[5];
    const float* Wul    = (const float*)d_in[6];
    const float* bul    = (const float*)d_in[7];
    const float* Wur    = (const float*)d_in[8];
    const float* bur    = (const float*)d_in[9];
    const float* conv_w = (const float*)d_in[10];
    const float* conv_b = (const float*)d_in[11];
    const float* Wskip  = (const float*)d_in[12];
    const float* Wi     = (const float*)d_in[13];
    const float* bi     = (const float*)d_in[14];
    const float* Wf     = (const float*)d_in[15];
    const float* bf     = (const float*)d_in[16];
    const float* Wo     = (const float*)d_in[17];
    const float* bo     = (const float*)d_in[18];
    const float* Wq     = (const float*)d_in[19];
    const float* bq     = (const float*)d_in[20];
    const float* Wk     = (const float*)d_in[21];
    const float* bk     = (const float*)d_in[22];
    const float* Wv     = (const float*)d_in[23];
    const float* bv     = (const float*)d_in[24];
    const float* gn_g   = (const float*)d_in[25];
    const float* gn_b   = (const float*)d_in[26];
    const float* Wd     = (const float*)d_in[27];
    const float* bd     = (const float*)d_in[28];

    float* out   = (float*)d_out;
    float* c_out = out + (size_t)B * DIM;
    float* n_out = c_out + (size_t)B * H * D * D;
    float* m_out = n_out + (size_t)B * H * D;

    float *xn, *xt, *xc, *rt, *qq, *kk, *vv, *oo, *sk, *iee, *fee, *yy, *p0, *p1;
    cudaGetSymbolAddress((void**)&xn,  g_xn);
    cudaGetSymbolAddress((void**)&xt,  g_xt);
    cudaGetSymbolAddress((void**)&xc,  g_xc);
    cudaGetSymbolAddress((void**)&rt,  g_rt);
    cudaGetSymbolAddress((void**)&qq,  g_q);
    cudaGetSymbolAddress((void**)&kk,  g_k);
    cudaGetSymbolAddress((void**)&vv,  g_v);
    cudaGetSymbolAddress((void**)&oo,  g_o);
    cudaGetSymbolAddress((void**)&sk,  g_sk);
    cudaGetSymbolAddress((void**)&iee, g_ie);
    cudaGetSymbolAddress((void**)&fee, g_fe);
    cudaGetSymbolAddress((void**)&yy,  g_y);
    cudaGetSymbolAddress((void**)&p0,  g_p0);
    cudaGetSymbolAddress((void**)&p1,  g_p1);

    cudaFuncSetAttribute(gemm_mma<64, 128, 256>,
                         cudaFuncAttributeMaxDynamicSharedMemorySize, SMEM_A);
    cudaFuncSetAttribute(gemm_mma<64, 64, 128>,
                         cudaFuncAttributeMaxDynamicSharedMemorySize, SMEM_B);
    cudaFuncSetAttribute(gemm_mma<128, 64, 128>,
                         cudaFuncAttributeMaxDynamicSharedMemorySize, SMEM_C);

    // 1. layernorm
    ln_kernel<<<B, 256>>>(seq, ln_g, ln_b, xn);

    // 2+3. x_t = xn@Wul^T+bul [B,P] and r_t = xn@Wur^T+bur [B,HD]
    {
        GemmArgs a{};
        a.d[0] = {xn, Wul, bul, nullptr, xt, P,  DIM, DIM / 32, 0};
        a.d[1] = {xn, Wur, bur, nullptr, rt, HD, DIM, DIM / 32, 0};
        gemm_mma<64, 128, 256><<<dim3(P / 128, B / 64, 2), 256, SMEM_A>>>(a);
    }

    // 4+5. fused causal conv + silu + i/f gates
    conv_if_kernel<<<B, 256>>>(xt, conv_w, conv_b, xc,
                               Wi, bi, Wf, bf, m_tm1, m_out, iee, fee);

    // 6. batched 5x GEMM (N=1024, K=2048) K-split x2, 128x64 tiles -> 320 CTAs
    {
        const float* As[5] = {xc, xc, xt, xt, xc};
        const float* Ws[5] = {Wq, Wk, Wv, Wo, Wskip};
        GemmArgs a{};
        for (int i = 0; i < 5; i++) {
            a.d[i]     = {As[i],        Ws[i],        nullptr, nullptr,
                          p0 + (size_t)i * SEG, HD, P, 32, 0};
            a.d[i + 5] = {As[i] + 1024, Ws[i] + 1024, nullptr, nullptr,
                          p1 + (size_t)i * SEG, HD, P, 32, 0};
        }
        gemm_mma<128, 64, 128><<<dim3(HD / 64, B / 128, 10), 128, SMEM_C>>>(a);
    }
    {
        CArgs c{};
        c.e[0] = {p0 + 0 * SEG, p1 + 0 * SEG, bq, nullptr, qq, 0};
        c.e[1] = {p0 + 1 * SEG, p1 + 1 * SEG, bk, nullptr, kk, 0};
        c.e[2] = {p0 + 2 * SEG, p1 + 2 * SEG, bv, nullptr, vv, 0};
        c.e[3] = {p0 + 3 * SEG, p1 + 3 * SEG, bo, nullptr, oo, 1};
        c.e[4] = {p0 + 4 * SEG, p1 + 4 * SEG, nullptr, nullptr, sk, 0};
        combine_kernel<<<dim3(SEG / 4 / 256, 1, 5), 256>>>(c);
    }

    // 7. fused state update + readout + groupnorm + skip + silu(r) gate
    state_kernel<<<B * H, 128>>>(c_tm1, n_tm1, qq, kk, vv, oo, iee, fee,
                                 sk, rt, gn_g, gn_b, c_out, n_out, yy);

    // 8. out = y @ Wd^T + bd + seq : K-split x2 -> 128 CTAs + combine
    {
        GemmArgs a{};
        a.d[0] = {yy,       Wd,       nullptr, nullptr, p0 + 5 * SEG, DIM, HD, 16, 0};
        a.d[1] = {yy + 512, Wd + 512, nullptr, nullptr, p1 + 5 * SEG, DIM, HD, 16, 0};
        gemm_mma<64, 64, 128><<<dim3(DIM / 64, B / 64, 2), 128, SMEM_B>>>(a);
    }
    {
        CArgs c{};
        c.e[0] = {p0 + 5 * SEG, p1 + 5 * SEG, bd, seq, out, 0};
        combine_kernel<<<dim3(SEG / 4 / 256, 1, 1), 256>>>(c);
    }
}

// round 11
// speedup vs baseline: 1.0753x; 1.0753x over previous
#include <cuda_runtime.h>
#include <cuda_bf16.h>
#include <math.h>
#include <stdint.h>

#define B 256
#define DIM 1024
#define H 8
#define D 128
#define P 2048
#define HD 1024
#define KER 4

// ---------------- scratch (static device memory; no allocs) ----------------
__device__ float g_xn[B * DIM];
__device__ float g_xt[B * P];
__device__ float g_xc[B * P];
__device__ float g_rt[B * HD];
__device__ float g_ie[B * H];
__device__ float g_fe[B * H];
__device__ float g_y[B * HD];
#define SEG (B * HD)
__device__ float g_p0[6 * SEG];
__device__ float g_p1[6 * SEG];

__device__ __forceinline__ uint32_t smem_u32(const void* p) {
    uint32_t a;
    asm("{ .reg .u64 t; cvta.to.shared.u64 t, %1; cvt.u32.u64 %0, t; }" : "=r"(a) : "l"(p));
    return a;
}

#define LDM4(r, a) \
    asm volatile("ldmatrix.sync.aligned.m8n8.x4.shared.b16 {%0,%1,%2,%3}, [%4];" \
        : "=r"((r)[0]), "=r"((r)[1]), "=r"((r)[2]), "=r"((r)[3]) : "r"(a))

#define MMA(d, a, b0, b1) \
    asm volatile("mma.sync.aligned.m16n8k16.row.col.f32.bf16.bf16.f32 " \
        "{%0,%1,%2,%3}, {%4,%5,%6,%7}, {%8,%9}, {%0,%1,%2,%3};" \
        : "+f"((d)[0]), "+f"((d)[1]), "+f"((d)[2]), "+f"((d)[3]) \
        : "r"((a)[0]), "r"((a)[1]), "r"((a)[2]), "r"((a)[3]), "r"(b0), "r"(b1))

// ================= layernorm =================
__global__ void ln_kernel(const float* __restrict__ x, const float* __restrict__ g,
                          const float* __restrict__ bta, float* __restrict__ out) {
    int row = blockIdx.x;
    int tid = threadIdx.x;
    const float4* xr = (const float4*)(x + (size_t)row * DIM);
    float4 v = xr[tid];
    float s  = v.x + v.y + v.z + v.w;
    float ss = v.x * v.x + v.y * v.y + v.z * v.z + v.w * v.w;
    __shared__ float shs[8], shss[8];
    __shared__ float mu_s, rstd_s;
    #pragma unroll
    for (int o = 16; o; o >>= 1) {
        s  += __shfl_down_sync(0xffffffffu, s, o);
        ss += __shfl_down_sync(0xffffffffu, ss, o);
    }
    int w = tid >> 5, lane = tid & 31;
    if (lane == 0) { shs[w] = s; shss[w] = ss; }
    __syncthreads();
    if (tid == 0) {
        float ts = 0.f, tss = 0.f;
        #pragma unroll
        for (int i = 0; i < 8; i++) { ts += shs[i]; tss += shss[i]; }
        float mu = ts * (1.f / DIM);
        float var = tss * (1.f / DIM) - mu * mu;
        mu_s = mu;
        rstd_s = rsqrtf(var + 1e-5f);
    }
    __syncthreads();
    float mu = mu_s, rs = rstd_s;
    float4 g4 = ((const float4*)g)[tid];
    float4 b4 = ((const float4*)bta)[tid];
    float4 r;
    r.x = (v.x - mu) * rs * g4.x + b4.x;
    r.y = (v.y - mu) * rs * g4.y + b4.y;
    r.z = (v.z - mu) * rs * g4.z + b4.z;
    r.w = (v.w - mu) * rs * g4.w + b4.w;
    ((float4*)(out + (size_t)row * DIM))[tid] = r;
}

// ================= tensor-core GEMM NT via mma.sync =======
// C[M,N] = A[M,K] @ W[N,K]^T, fp32 in/out, bf16 hi/lo split (3 MMA terms)
struct GemmDesc {
    const float* A;      // pre-offset by k0
    const float* W;      // pre-offset by k0
    const float* bias;   // nullable
    const float* res;    // nullable
    float* C;
    int N;
    int ldk;
    int kn;
    int epi;             // 0 none, 1 sigmoid
};
struct GemmArgs { GemmDesc d[10]; };

// global -> regs: TM rows x 32 fp32; thread handles (row, 8-float granule)
template<int CNT2, int NTHR>
__device__ __forceinline__ void ldg_rows2(const float* __restrict__ g, int ldk, int k0,
                                          float4 (&p)[CNT2 * 2], int tid) {
    #pragma unroll
    for (int i = 0; i < CNT2; i++) {
        int idx = tid + i * NTHR;
        int r = idx >> 2, g8 = idx & 3;
        const float* src = g + (size_t)r * ldk + k0 + g8 * 8;
        p[2 * i]     = *(const float4*)(src);
        p[2 * i + 1] = *(const float4*)(src + 4);
    }
}
// regs -> bf16 hi/lo -> padded SMEM (80B row stride), STS.128 per plane
template<int CNT2, int NTHR>
__device__ __forceinline__ void cvt_sts2(const float4 (&p)[CNT2 * 2], char* hi, char* lo,
                                         int tid) {
    #pragma unroll
    for (int i = 0; i < CNT2; i++) {
        int idx = tid + i * NTHR;
        int r = idx >> 2, g8 = idx & 3;
        float4 v0 = p[2 * i], v1 = p[2 * i + 1];
        uint32_t a0 = __float_as_uint(v0.x), a1 = __float_as_uint(v0.y);
        uint32_t a2 = __float_as_uint(v0.z), a3 = __float_as_uint(v0.w);
        uint32_t b0 = __float_as_uint(v1.x), b1 = __float_as_uint(v1.y);
        uint32_t b2 = __float_as_uint(v1.z), b3 = __float_as_uint(v1.w);
        uint4 hv;
        hv.x = __byte_perm(a0, a1, 0x7632);
        hv.y = __byte_perm(a2, a3, 0x7632);
        hv.z = __byte_perm(b0, b1, 0x7632);
        hv.w = __byte_perm(b2, b3, 0x7632);
        float r0 = v0.x - __uint_as_float(a0 & 0xffff0000u);
        float r1 = v0.y - __uint_as_float(a1 & 0xffff0000u);
        float r2 = v0.z - __uint_as_float(a2 & 0xffff0000u);
        float r3 = v0.w - __uint_as_float(a3 & 0xffff0000u);
        float r4 = v1.x - __uint_as_float(b0 & 0xffff0000u);
        float r5 = v1.y - __uint_as_float(b1 & 0xffff0000u);
        float r6 = v1.z - __uint_as_float(b2 & 0xffff0000u);
        float r7 = v1.w - __uint_as_float(b3 & 0xffff0000u);
        uint4 lv;
        asm("cvt.rn.bf16x2.f32 %0, %1, %2;" : "=r"(lv.x) : "f"(r1), "f"(r0));
        asm("cvt.rn.bf16x2.f32 %0, %1, %2;" : "=r"(lv.y) : "f"(r3), "f"(r2));
        asm("cvt.rn.bf16x2.f32 %0, %1, %2;" : "=r"(lv.z) : "f"(r5), "f"(r4));
        asm("cvt.rn.bf16x2.f32 %0, %1, %2;" : "=r"(lv.w) : "f"(r7), "f"(r6));
        int off = r * 80 + g8 * 16;
        *(uint4*)(hi + off) = hv;
        *(uint4*)(lo + off) = lv;
    }
}

template<int TM, int TN, int NTHR>
__global__ __launch_bounds__(NTHR, (NTHR == 128) ? 3 : 1) void gemm_mma(GemmArgs args) {
    extern __shared__ char smem[];
    constexpr int MATA = TM * 80;
    constexpr int MATW = TN * 80;
    constexpr int STG = 2 * (MATA + MATW);
    constexpr int CA2 = TM * 4 / NTHR;
    constexpr int CW2 = TN * 4 / NTHR;
    constexpr int MW = TM / 32;

    const GemmDesc dd = args.d[blockIdx.z];
    const int N = dd.N, ldk = dd.ldk;
    const int bn0 = blockIdx.x * TN;
    const int bm0 = blockIdx.y * TM;
    if (bn0 >= N) return;

    const int tid = threadIdx.x;
    const int wid = tid >> 5, lane = tid & 31;
    const int m0 = (wid % MW) * 32;
    const int n0 = (wid / MW) * 32;
    const int grp = lane >> 3, lrow = lane & 7;
    const uint32_t sbase = smem_u32(smem);

    const float* Ag = dd.A + (size_t)bm0 * ldk;
    const float* Wg = dd.W + (size_t)bn0 * ldk;

    uint32_t aoff[2], boff[2];
    #pragma unroll
    for (int mi = 0; mi < 2; mi++)
        aoff[mi] = (uint32_t)((m0 + mi * 16 + (grp & 1) * 8 + lrow) * 80 + (grp >> 1) * 16);
    #pragma unroll
    for (int bi = 0; bi < 2; bi++)
        boff[bi] = (uint32_t)((n0 + bi * 16 + (grp >> 1) * 8 + lrow) * 80 + (grp & 1) * 16);

    float acc[2][4][4];
    #pragma unroll
    for (int mi = 0; mi < 2; mi++)
        #pragma unroll
        for (int ni = 0; ni < 4; ni++)
            acc[mi][ni][0] = acc[mi][ni][1] = acc[mi][ni][2] = acc[mi][ni][3] = 0.f;

    const int nk = dd.kn;
    // prologue: fill stage 0
    {
        float4 pA[CA2 * 2], pW[CW2 * 2];
        ldg_rows2<CA2, NTHR>(Ag, ldk, 0, pA, tid);
        ldg_rows2<CW2, NTHR>(Wg, ldk, 0, pW, tid);
        cvt_sts2<CA2, NTHR>(pA, smem, smem + MATA, tid);
        cvt_sts2<CW2, NTHR>(pW, smem + 2 * MATA, smem + 2 * MATA + MATW, tid);
    }
    __syncthreads();

    for (int it = 0; it < nk; it++) {
        float4 pA[CA2 * 2], pW[CW2 * 2];
        if (it + 1 < nk) {
            ldg_rows2<CA2, NTHR>(Ag, ldk, (it + 1) << 5, pA, tid);
            ldg_rows2<CW2, NTHR>(Wg, ldk, (it + 1) << 5, pW, tid);
        }
        const uint32_t sA  = sbase + (it & 1) * STG;
        const uint32_t sAl = sA + MATA, sWh = sA + 2 * MATA, sWl = sA + 2 * MATA + MATW;
        #pragma unroll
        for (int ks = 0; ks < 2; ks++) {
            const uint32_t kb = ks * 32;
            uint32_t Ah[2][4], Al[2][4], Bh[4][2], Bl[4][2];
            #pragma unroll
            for (int mi = 0; mi < 2; mi++) {
                LDM4(Ah[mi], sA  + aoff[mi] + kb);
                LDM4(Al[mi], sAl + aoff[mi] + kb);
            }
            #pragma unroll
            for (int bi = 0; bi < 2; bi++) {
                uint32_t t[4];
                LDM4(t, sWh + boff[bi] + kb);
                Bh[2 * bi][0] = t[0]; Bh[2 * bi][1] = t[1];
                Bh[2 * bi + 1][0] = t[2]; Bh[2 * bi + 1][1] = t[3];
                LDM4(t, sWl + boff[bi] + kb);
                Bl[2 * bi][0] = t[0]; Bl[2 * bi][1] = t[1];
                Bl[2 * bi + 1][0] = t[2]; Bl[2 * bi + 1][1] = t[3];
            }
            #pragma unroll
            for (int mi = 0; mi < 2; mi++)
                #pragma unroll
                for (int ni = 0; ni < 4; ni++) {
                    MMA(acc[mi][ni], Ah[mi], Bh[ni][0], Bh[ni][1]);
                    MMA(acc[mi][ni], Ah[mi], Bl[ni][0], Bl[ni][1]);
                    MMA(acc[mi][ni], Al[mi], Bh[ni][0], Bh[ni][1]);
                }
        }
        if (it + 1 < nk) {
            char* st = smem + ((it + 1) & 1) * STG;
            cvt_sts2<CA2, NTHR>(pA, st, st + MATA, tid);
            cvt_sts2<CW2, NTHR>(pW, st + 2 * MATA, st + 2 * MATA + MATW, tid);
        }
        __syncthreads();
    }

    // epilogue
    const int qrow = lane >> 2, qcol = (lane & 3) * 2;
    #pragma unroll
    for (int ni = 0; ni < 4; ni++) {
        const int c = bn0 + n0 + ni * 8 + qcol;
        float2 bb = make_float2(0.f, 0.f);
        if (dd.bias) bb = *(const float2*)(dd.bias + c);
        #pragma unroll
        for (int mi = 0; mi < 2; mi++) {
            const int r = bm0 + m0 + mi * 16 + qrow;
            float v0 = acc[mi][ni][0] + bb.x;
            float v1 = acc[mi][ni][1] + bb.y;
            float v2 = acc[mi][ni][2] + bb.x;
            float v3 = acc[mi][ni][3] + bb.y;
            if (dd.epi == 1) {
                v0 = 1.f / (1.f + expf(-v0)); v1 = 1.f / (1.f + expf(-v1));
                v2 = 1.f / (1.f + expf(-v2)); v3 = 1.f / (1.f + expf(-v3));
            }
            if (dd.res) {
                float2 r0 = *(const float2*)(dd.res + (size_t)r * N + c);
                float2 r1 = *(const float2*)(dd.res + (size_t)(r + 8) * N + c);
                v0 += r0.x; v1 += r0.y; v2 += r1.x; v3 += r1.y;
            }
            *(float2*)(dd.C + (size_t)r * N + c) = make_float2(v0, v1);
            *(float2*)(dd.C + (size_t)(r + 8) * N + c) = make_float2(v2, v3);
        }
    }
}

#define SMEM_A (2 * 2 * (64 * 80 + 128 * 80))   // <64,128>: 61440
#define SMEM_B (2 * 2 * (64 * 80 + 64 * 80))    // <64,64>:  40960

// ================= combine: C = p0 + p1 + bias + res (Wd only) =============
__global__ __launch_bounds__(256) void combine_kernel(
        const float* __restrict__ p0, const float* __restrict__ p1,
        const float* __restrict__ bias, const float* __restrict__ res,
        float* __restrict__ C) {
    int i = blockIdx.x * 256 + threadIdx.x;      // float4 index, N = 1024
    float4 x = ((const float4*)p0)[i];
    float4 y = ((const float4*)p1)[i];
    float4 b = ((const float4*)bias)[i & 255];
    float4 r = ((const float4*)res)[i];
    ((float4*)C)[i] = make_float4(x.x + y.x + b.x + r.x, x.y + y.y + b.y + r.y,
                                  x.z + y.z + b.z + r.z, x.w + y.w + b.w + r.w);
}

// ================= fused causal conv (k=4) + silu + i/f gates ================
__global__ __launch_bounds__(256) void conv_if_kernel(
        const float* __restrict__ xt, const float* __restrict__ w,
        const float* __restrict__ cb, float* __restrict__ xc,
        const float* __restrict__ Wi, const float* __restrict__ bi,
        const float* __restrict__ Wf, const float* __restrict__ bfb,
        const float* __restrict__ m_tm1, float* __restrict__ m_out,
        float* __restrict__ ie, float* __restrict__ fe) {
    __shared__ float sx[P];
    __shared__ float sc[P];
    int b = blockIdx.x;
    int tid = threadIdx.x;
    const float4* xr = (const float4*)(xt + (size_t)b * P);
    #pragma unroll
    for (int i = 0; i < P / 4 / 256; i++)
        ((float4*)sx)[tid + i * 256] = xr[tid + i * 256];
    float w0 = w[0], w1 = w[1], w2 = w[2], w3 = w[3], cbv = cb[0];
    __syncthreads();
    #pragma unroll
    for (int i = 0; i < P / 256; i++) {
        int p = tid + i * 256;
        float acc = cbv + w3 * sx[p];
        if (p >= 1) acc += w2 * sx[p - 1];
        if (p >= 2) acc += w1 * sx[p - 2];
        if (p >= 3) acc += w0 * sx[p - 3];
        float s = acc / (1.f + expf(-acc));
        sc[p] = s;
        xc[(size_t)b * P + p] = s;
    }
    __syncthreads();
    int h = tid >> 5, lane = tid & 31;
    const float* wi = Wi + (size_t)h * P;
    const float* wf = Wf + (size_t)h * P;
    float ai = 0.f, af = 0.f;
    #pragma unroll
    for (int k = lane * 4; k < P; k += 128) {
        float4 xv  = *(const float4*)(sc + k);
        float4 wiv = *(const float4*)(wi + k);
        float4 wfv = *(const float4*)(wf + k);
        ai += xv.x * wiv.x + xv.y * wiv.y + xv.z * wiv.z + xv.w * wiv.w;
        af += xv.x * wfv.x + xv.y * wfv.y + xv.z * wfv.z + xv.w * wfv.w;
    }
    #pragma unroll
    for (int o = 16; o; o >>= 1) {
        ai += __shfl_down_sync(0xffffffffu, ai, o);
        af += __shfl_down_sync(0xffffffffu, af, o);
    }
    if (lane == 0) {
        int bh = b * H + h;
        float i_t = ai + bi[h];
        float f_t = af + bfb[h];
        float mp = m_tm1[bh];
        float m = fmaxf(f_t + mp, i_t);
        m_out[bh] = m;
        ie[bh] = expf(i_t - m);
        fe[bh] = expf(f_t - m + mp);
    }
}

// ================= fused combine + state update + readout + groupnorm =======
// reads raw GEMM partials (q,k,v,o,sk at SEG offsets 0..4 in p0/p1) + biases
__global__ __launch_bounds__(128) void state_kernel(
    const float* __restrict__ c_tm1, const float* __restrict__ n_tm1,
    const float* __restrict__ p0, const float* __restrict__ p1,
    const float* __restrict__ bq, const float* __restrict__ bk,
    const float* __restrict__ bv, const float* __restrict__ bo,
    const float* __restrict__ ie_, const float* __restrict__ fe_,
    const float* __restrict__ r,
    const float* __restrict__ gn_g, const float* __restrict__ gn_b,
    float* __restrict__ c_out, float* __restrict__ n_out, float* __restrict__ y) {
    int bh = blockIdx.x;
    int b = bh >> 3, h = bh & 7;
    __shared__ float qs[D], ks[D], vs[D], hnum[D];
    __shared__ float red[4], rs1[4], rs2[4];
    int tid = threadIdx.x;
    int base = b * HD + h * D;
    int hb = h * D + tid;
    // inline combine of partials
    qs[tid] = p0[0 * SEG + base + tid] + p1[0 * SEG + base + tid] + bq[hb];
    ks[tid] = (p0[1 * SEG + base + tid] + p1[1 * SEG + base + tid] + bk[hb])
              * 0.08838834764831845f;   // 1/sqrt(128)
    vs[tid] = p0[2 * SEG + base + tid] + p1[2 * SEG + base + tid] + bv[hb];
    float ov = p0[3 * SEG + base + tid] + p1[3 * SEG + base + tid] + bo[hb];
    ov = 1.f / (1.f + expf(-ov));
    float skv = p0[4 * SEG + base + tid] + p1[4 * SEG + base + tid];
    float ie = ie_[bh], fe = fe_[bh];
    __syncthreads();

    const float4* crow = (const float4*)(c_tm1 + (size_t)bh * D * D);
    float4* cout = (float4*)(c_out + (size_t)bh * D * D);
    int w = tid >> 5, lane = tid & 31;
    float4 k4 = ((const float4*)ks)[lane];
    float4 q4 = ((const float4*)qs)[lane];
    #pragma unroll 4
    for (int it = 0; it < 32; it++) {
        int d = it * 4 + w;
        float4 c4 = crow[d * 32 + lane];
        float ivd = ie * vs[d];
        float4 cn;
        cn.x = fe * c4.x + ivd * k4.x;
        cn.y = fe * c4.y + ivd * k4.y;
        cn.z = fe * c4.z + ivd * k4.z;
        cn.w = fe * c4.w + ivd * k4.w;
        cout[d * 32 + lane] = cn;
        float part = cn.x * q4.x + cn.y * q4.y + cn.z * q4.z + cn.w * q4.w;
        #pragma unroll
        for (int off = 16; off; off >>= 1) part += __shfl_down_sync(0xffffffffu, part, off);
        if (lane == 0) hnum[d] = part;
    }
    __syncthreads();

    int d = tid;
    float nv = fe * n_tm1[bh * D + d] + ie * ks[d];
    n_out[bh * D + d] = nv;
    float dn = nv * qs[d];
    #pragma unroll
    for (int off = 16; off; off >>= 1) dn += __shfl_down_sync(0xffffffffu, dn, off);
    if (lane == 0) red[w] = dn;
    __syncthreads();
    float denom = fmaxf(red[0] + red[1] + red[2] + red[3], 1.0f);
    float ht = ov * hnum[d] / denom;

    float s1 = ht, s2 = ht * ht;
    #pragma unroll
    for (int off = 16; off; off >>= 1) {
        s1 += __shfl_down_sync(0xffffffffu, s1, off);
        s2 += __shfl_down_sync(0xffffffffu, s2, off);
    }
    if (lane == 0) { rs1[w] = s1; rs2[w] = s2; }
    __syncthreads();
    float mu  = (rs1[0] + rs1[1] + rs1[2] + rs1[3]) * (1.f / D);
    float var = (rs2[0] + rs2[1] + rs2[2] + rs2[3]) * (1.f / D) - mu * mu;
    float rstd = rsqrtf(var + 1e-5f);
    float xn = (ht - mu) * rstd * gn_g[hb] + gn_b[hb];
    float rv = r[base + d];
    float yv = (xn + skv) * (rv / (1.f + expf(-rv)));
    y[base + d] = yv;
}

// ---------------------------------------------------------------------------
extern "C" void kernel_launch(void* const* d_in, const int* in_sizes, int n_in,
                              void* d_out, int out_size) {
    const float* seq    = (const float*)d_in[0];
    const float* c_tm1  = (const float*)d_in[1];
    const float* n_tm1  = (const float*)d_in[2];
    const float* m_tm1  = (const float*)d_in[3];
    const float* ln_g   = (const float*)d_in[4];
    const float* ln_b   = (const float*)d_in[5];
    const float* Wul    = (const float*)d_in[6];
    const float* bul    = (const float*)d_in[7];
    const float* Wur    = (const float*)d_in[8];
    const float* bur    = (const float*)d_in[9];
    const float* conv_w = (const float*)d_in[10];
    const float* conv_b = (const float*)d_in[11];
    const float* Wskip  = (const float*)d_in[12];
    const float* Wi     = (const float*)d_in[13];
    const float* bi     = (const float*)d_in[14];
    const float* Wf     = (const float*)d_in[15];
    const float* bf     = (const float*)d_in[16];
    const float* Wo     = (const float*)d_in[17];
    const float* bo     = (const float*)d_in[18];
    const float* Wq     = (const float*)d_in[19];
    const float* bq     = (const float*)d_in[20];
    const float* Wk     = (const float*)d_in[21];
    const float* bk     = (const float*)d_in[22];
    const float* Wv     = (const float*)d_in[23];
    const float* bv     = (const float*)d_in[24];
    const float* gn_g   = (const float*)d_in[25];
    const float* gn_b   = (const float*)d_in[26];
    const float* Wd     = (const float*)d_in[27];
    const float* bd     = (const float*)d_in[28];

    float* out   = (float*)d_out;
    float* c_out = out + (size_t)B * DIM;
    float* n_out = c_out + (size_t)B * H * D * D;
    float* m_out = n_out + (size_t)B * H * D;

    float *xn, *xt, *xc, *rt, *iee, *fee, *yy, *p0, *p1;
    cudaGetSymbolAddress((void**)&xn,  g_xn);
    cudaGetSymbolAddress((void**)&xt,  g_xt);
    cudaGetSymbolAddress((void**)&xc,  g_xc);
    cudaGetSymbolAddress((void**)&rt,  g_rt);
    cudaGetSymbolAddress((void**)&iee, g_ie);
    cudaGetSymbolAddress((void**)&fee, g_fe);
    cudaGetSymbolAddress((void**)&yy,  g_y);
    cudaGetSymbolAddress((void**)&p0,  g_p0);
    cudaGetSymbolAddress((void**)&p1,  g_p1);

    cudaFuncSetAttribute(gemm_mma<64, 128, 256>,
                         cudaFuncAttributeMaxDynamicSharedMemorySize, SMEM_A);
    cudaFuncSetAttribute(gemm_mma<64, 64, 128>,
                         cudaFuncAttributeMaxDynamicSharedMemorySize, SMEM_B);

    // 1. layernorm
    ln_kernel<<<B, 256>>>(seq, ln_g, ln_b, xn);

    // 2+3. x_t = xn@Wul^T+bul [B,P] and r_t = xn@Wur^T+bur [B,HD]
    {
        GemmArgs a{};
        a.d[0] = {xn, Wul, bul, nullptr, xt, P,  DIM, DIM / 32, 0};
        a.d[1] = {xn, Wur, bur, nullptr, rt, HD, DIM, DIM / 32, 0};
        gemm_mma<64, 128, 256><<<dim3(P / 128, B / 64, 2), 256, SMEM_A>>>(a);
    }

    // 4+5. fused causal conv + silu + i/f gates
    conv_if_kernel<<<B, 256>>>(xt, conv_w, conv_b, xc,
                               Wi, bi, Wf, bf, m_tm1, m_out, iee, fee);

    // 6. batched 5x GEMM (N=1024, K=2048) K-split x2 -> 640 CTAs, raw partials
    {
        const float* As[5] = {xc, xc, xt, xt, xc};
        const float* Ws[5] = {Wq, Wk, Wv, Wo, Wskip};
        GemmArgs a{};
        for (int i = 0; i < 5; i++) {
            a.d[i]     = {As[i],        Ws[i],        nullptr, nullptr,
                          p0 + (size_t)i * SEG, HD, P, 32, 0};
            a.d[i + 5] = {As[i] + 1024, Ws[i] + 1024, nullptr, nullptr,
                          p1 + (size_t)i * SEG, HD, P, 32, 0};
        }
        gemm_mma<64, 64, 128><<<dim3(HD / 64, B / 64, 10), 128, SMEM_B>>>(a);
    }

    // 7. fused combine + state update + readout + groupnorm + skip + gate
    state_kernel<<<B * H, 128>>>(c_tm1, n_tm1, p0, p1, bq, bk, bv, bo,
                                 iee, fee, rt, gn_g, gn_b, c_out, n_out, yy);

    // 8. out = y @ Wd^T + bd + seq : K-split x2 -> 128 CTAs + combine
    {
        GemmArgs a{};
        a.d[0] = {yy,       Wd,       nullptr, nullptr, p0 + 5 * SEG, DIM, HD, 16, 0};
        a.d[1] = {yy + 512, Wd + 512, nullptr, nullptr, p1 + 5 * SEG, DIM, HD, 16, 0};
        gemm_mma<64, 64, 128><<<dim3(DIM / 64, B / 64, 2), 128, SMEM_B>>>(a);
    }
    combine_kernel<<<SEG / 4 / 256, 256>>>(p0 + 5 * SEG, p1 + 5 * SEG, bd, seq, out);
}

// round 12
// speedup vs baseline: 1.1000x; 1.0230x over previous
#include <cuda_runtime.h>
#include <cuda_bf16.h>
#include <math.h>
#include <stdint.h>

#define B 256
#define DIM 1024
#define H 8
#define D 128
#define P 2048
#define HD 1024
#define KER 4

// ---------------- scratch (static device memory; no allocs) ----------------
__device__ float g_xn[B * DIM];
__device__ float g_xt[B * P];
__device__ float g_xc[B * P];
__device__ float g_rt[B * HD];
__device__ float g_ie[B * H];
__device__ float g_fe[B * H];
__device__ float g_y[B * HD];
#define SEG (B * HD)
__device__ float g_p0[6 * SEG];
__device__ float g_p1[6 * SEG];

__device__ __forceinline__ uint32_t smem_u32(const void* p) {
    uint32_t a;
    asm("{ .reg .u64 t; cvta.to.shared.u64 t, %1; cvt.u32.u64 %0, t; }" : "=r"(a) : "l"(p));
    return a;
}

#define LDM4(r, a) \
    asm volatile("ldmatrix.sync.aligned.m8n8.x4.shared.b16 {%0,%1,%2,%3}, [%4];" \
        : "=r"((r)[0]), "=r"((r)[1]), "=r"((r)[2]), "=r"((r)[3]) : "r"(a))

#define MMA(d, a, b0, b1) \
    asm volatile("mma.sync.aligned.m16n8k16.row.col.f32.bf16.bf16.f32 " \
        "{%0,%1,%2,%3}, {%4,%5,%6,%7}, {%8,%9}, {%0,%1,%2,%3};" \
        : "+f"((d)[0]), "+f"((d)[1]), "+f"((d)[2]), "+f"((d)[3]) \
        : "r"((a)[0]), "r"((a)[1]), "r"((a)[2]), "r"((a)[3]), "r"(b0), "r"(b1))

// ================= layernorm =================
__global__ void ln_kernel(const float* __restrict__ x, const float* __restrict__ g,
                          const float* __restrict__ bta, float* __restrict__ out) {
    int row = blockIdx.x;
    int tid = threadIdx.x;
    const float4* xr = (const float4*)(x + (size_t)row * DIM);
    float4 v = xr[tid];
    float s  = v.x + v.y + v.z + v.w;
    float ss = v.x * v.x + v.y * v.y + v.z * v.z + v.w * v.w;
    __shared__ float shs[8], shss[8];
    __shared__ float mu_s, rstd_s;
    #pragma unroll
    for (int o = 16; o; o >>= 1) {
        s  += __shfl_down_sync(0xffffffffu, s, o);
        ss += __shfl_down_sync(0xffffffffu, ss, o);
    }
    int w = tid >> 5, lane = tid & 31;
    if (lane == 0) { shs[w] = s; shss[w] = ss; }
    __syncthreads();
    if (tid == 0) {
        float ts = 0.f, tss = 0.f;
        #pragma unroll
        for (int i = 0; i < 8; i++) { ts += shs[i]; tss += shss[i]; }
        float mu = ts * (1.f / DIM);
        float var = tss * (1.f / DIM) - mu * mu;
        mu_s = mu;
        rstd_s = rsqrtf(var + 1e-5f);
    }
    __syncthreads();
    float mu = mu_s, rs = rstd_s;
    float4 g4 = ((const float4*)g)[tid];
    float4 b4 = ((const float4*)bta)[tid];
    float4 r;
    r.x = (v.x - mu) * rs * g4.x + b4.x;
    r.y = (v.y - mu) * rs * g4.y + b4.y;
    r.z = (v.z - mu) * rs * g4.z + b4.z;
    r.w = (v.w - mu) * rs * g4.w + b4.w;
    ((float4*)(out + (size_t)row * DIM))[tid] = r;
}

// ================= tensor-core GEMM NT via mma.sync =======
// C[M,N] = A[M,K] @ W[N,K]^T, fp32 in/out, bf16 hi/lo split (3 MMA terms)
struct GemmDesc {
    const float* A;      // pre-offset by k0
    const float* W;      // pre-offset by k0
    const float* bias;   // nullable
    const float* res;    // nullable
    float* C;
    int N;
    int ldk;
    int kn;
    int epi;             // 0 none, 1 sigmoid
};
struct GemmArgs { GemmDesc d[10]; };

// global -> regs: TM rows x 32 fp32; thread handles (row, 8-float granule)
template<int CNT2, int NTHR>
__device__ __forceinline__ void ldg_rows2(const float* __restrict__ g, int ldk, int k0,
                                          float4 (&p)[CNT2 * 2], int tid) {
    #pragma unroll
    for (int i = 0; i < CNT2; i++) {
        int idx = tid + i * NTHR;
        int r = idx >> 2, g8 = idx & 3;
        const float* src = g + (size_t)r * ldk + k0 + g8 * 8;
        p[2 * i]     = *(const float4*)(src);
        p[2 * i + 1] = *(const float4*)(src + 4);
    }
}
// regs -> bf16 hi/lo -> padded SMEM (80B row stride), STS.128 per plane
template<int CNT2, int NTHR>
__device__ __forceinline__ void cvt_sts2(const float4 (&p)[CNT2 * 2], char* hi, char* lo,
                                         int tid) {
    #pragma unroll
    for (int i = 0; i < CNT2; i++) {
        int idx = tid + i * NTHR;
        int r = idx >> 2, g8 = idx & 3;
        float4 v0 = p[2 * i], v1 = p[2 * i + 1];
        uint32_t a0 = __float_as_uint(v0.x), a1 = __float_as_uint(v0.y);
        uint32_t a2 = __float_as_uint(v0.z), a3 = __float_as_uint(v0.w);
        uint32_t b0 = __float_as_uint(v1.x), b1 = __float_as_uint(v1.y);
        uint32_t b2 = __float_as_uint(v1.z), b3 = __float_as_uint(v1.w);
        uint4 hv;
        hv.x = __byte_perm(a0, a1, 0x7632);
        hv.y = __byte_perm(a2, a3, 0x7632);
        hv.z = __byte_perm(b0, b1, 0x7632);
        hv.w = __byte_perm(b2, b3, 0x7632);
        float r0 = v0.x - __uint_as_float(a0 & 0xffff0000u);
        float r1 = v0.y - __uint_as_float(a1 & 0xffff0000u);
        float r2 = v0.z - __uint_as_float(a2 & 0xffff0000u);
        float r3 = v0.w - __uint_as_float(a3 & 0xffff0000u);
        float r4 = v1.x - __uint_as_float(b0 & 0xffff0000u);
        float r5 = v1.y - __uint_as_float(b1 & 0xffff0000u);
        float r6 = v1.z - __uint_as_float(b2 & 0xffff0000u);
        float r7 = v1.w - __uint_as_float(b3 & 0xffff0000u);
        uint4 lv;
        asm("cvt.rn.bf16x2.f32 %0, %1, %2;" : "=r"(lv.x) : "f"(r1), "f"(r0));
        asm("cvt.rn.bf16x2.f32 %0, %1, %2;" : "=r"(lv.y) : "f"(r3), "f"(r2));
        asm("cvt.rn.bf16x2.f32 %0, %1, %2;" : "=r"(lv.z) : "f"(r5), "f"(r4));
        asm("cvt.rn.bf16x2.f32 %0, %1, %2;" : "=r"(lv.w) : "f"(r7), "f"(r6));
        int off = r * 80 + g8 * 16;
        *(uint4*)(hi + off) = hv;
        *(uint4*)(lo + off) = lv;
    }
}

template<int TM, int TN, int NTHR>
__global__ __launch_bounds__(NTHR, (NTHR == 128) ? 3 : ((TM == 128) ? 2 : 1))
void gemm_mma(GemmArgs args) {
    extern __shared__ char smem[];
    constexpr int MATA = TM * 80;
    constexpr int MATW = TN * 80;
    constexpr int STG = 2 * (MATA + MATW);
    constexpr int CA2 = TM * 4 / NTHR;
    constexpr int CW2 = TN * 4 / NTHR;
    constexpr int MW = TM / 32;              // warps along M
    constexpr int NWZ = (NTHR / 32) / MW;    // warps along N
    constexpr int WN = TN / NWZ;             // warp tile N width (32 here)
    constexpr int NI = WN / 8;               // n8 fragments per warp
    constexpr int BLD = WN / 16;             // B LDM4s per plane per ks

    const GemmDesc dd = args.d[blockIdx.z];
    const int N = dd.N, ldk = dd.ldk;
    const int bn0 = blockIdx.x * TN;
    const int bm0 = blockIdx.y * TM;
    if (bn0 >= N) return;

    const int tid = threadIdx.x;
    const int wid = tid >> 5, lane = tid & 31;
    const int m0 = (wid % MW) * 32;
    const int n0 = (wid / MW) * WN;
    const int grp = lane >> 3, lrow = lane & 7;
    const uint32_t sbase = smem_u32(smem);

    const float* Ag = dd.A + (size_t)bm0 * ldk;
    const float* Wg = dd.W + (size_t)bn0 * ldk;

    uint32_t aoff[2], boff[BLD];
    #pragma unroll
    for (int mi = 0; mi < 2; mi++)
        aoff[mi] = (uint32_t)((m0 + mi * 16 + (grp & 1) * 8 + lrow) * 80 + (grp >> 1) * 16);
    #pragma unroll
    for (int bi = 0; bi < BLD; bi++)
        boff[bi] = (uint32_t)((n0 + bi * 16 + (grp >> 1) * 8 + lrow) * 80 + (grp & 1) * 16);

    float acc[2][NI][4];
    #pragma unroll
    for (int mi = 0; mi < 2; mi++)
        #pragma unroll
        for (int ni = 0; ni < NI; ni++)
            acc[mi][ni][0] = acc[mi][ni][1] = acc[mi][ni][2] = acc[mi][ni][3] = 0.f;

    const int nk = dd.kn;
    // prologue: fill stage 0
    {
        float4 pA[CA2 * 2], pW[CW2 * 2];
        ldg_rows2<CA2, NTHR>(Ag, ldk, 0, pA, tid);
        ldg_rows2<CW2, NTHR>(Wg, ldk, 0, pW, tid);
        cvt_sts2<CA2, NTHR>(pA, smem, smem + MATA, tid);
        cvt_sts2<CW2, NTHR>(pW, smem + 2 * MATA, smem + 2 * MATA + MATW, tid);
    }
    __syncthreads();

    for (int it = 0; it < nk; it++) {
        float4 pA[CA2 * 2], pW[CW2 * 2];
        if (it + 1 < nk) {
            ldg_rows2<CA2, NTHR>(Ag, ldk, (it + 1) << 5, pA, tid);
            ldg_rows2<CW2, NTHR>(Wg, ldk, (it + 1) << 5, pW, tid);
        }
        const uint32_t sA  = sbase + (it & 1) * STG;
        const uint32_t sAl = sA + MATA, sWh = sA + 2 * MATA, sWl = sA + 2 * MATA + MATW;
        #pragma unroll
        for (int ks = 0; ks < 2; ks++) {
            const uint32_t kb = ks * 32;
            uint32_t Ah[2][4], Al[2][4], Bh[NI][2], Bl[NI][2];
            #pragma unroll
            for (int mi = 0; mi < 2; mi++) {
                LDM4(Ah[mi], sA  + aoff[mi] + kb);
                LDM4(Al[mi], sAl + aoff[mi] + kb);
            }
            #pragma unroll
            for (int bi = 0; bi < BLD; bi++) {
                uint32_t t[4];
                LDM4(t, sWh + boff[bi] + kb);
                Bh[2 * bi][0] = t[0]; Bh[2 * bi][1] = t[1];
                Bh[2 * bi + 1][0] = t[2]; Bh[2 * bi + 1][1] = t[3];
                LDM4(t, sWl + boff[bi] + kb);
                Bl[2 * bi][0] = t[0]; Bl[2 * bi][1] = t[1];
                Bl[2 * bi + 1][0] = t[2]; Bl[2 * bi + 1][1] = t[3];
            }
            #pragma unroll
            for (int mi = 0; mi < 2; mi++)
                #pragma unroll
                for (int ni = 0; ni < NI; ni++) {
                    MMA(acc[mi][ni], Ah[mi], Bh[ni][0], Bh[ni][1]);
                    MMA(acc[mi][ni], Ah[mi], Bl[ni][0], Bl[ni][1]);
                    MMA(acc[mi][ni], Al[mi], Bh[ni][0], Bh[ni][1]);
                }
        }
        if (it + 1 < nk) {
            char* st = smem + ((it + 1) & 1) * STG;
            cvt_sts2<CA2, NTHR>(pA, st, st + MATA, tid);
            cvt_sts2<CW2, NTHR>(pW, st + 2 * MATA, st + 2 * MATA + MATW, tid);
        }
        __syncthreads();
    }

    // epilogue
    const int qrow = lane >> 2, qcol = (lane & 3) * 2;
    #pragma unroll
    for (int ni = 0; ni < NI; ni++) {
        const int c = bn0 + n0 + ni * 8 + qcol;
        float2 bb = make_float2(0.f, 0.f);
        if (dd.bias) bb = *(const float2*)(dd.bias + c);
        #pragma unroll
        for (int mi = 0; mi < 2; mi++) {
            const int r = bm0 + m0 + mi * 16 + qrow;
            float v0 = acc[mi][ni][0] + bb.x;
            float v1 = acc[mi][ni][1] + bb.y;
            float v2 = acc[mi][ni][2] + bb.x;
            float v3 = acc[mi][ni][3] + bb.y;
            if (dd.epi == 1) {
                v0 = 1.f / (1.f + expf(-v0)); v1 = 1.f / (1.f + expf(-v1));
                v2 = 1.f / (1.f + expf(-v2)); v3 = 1.f / (1.f + expf(-v3));
            }
            if (dd.res) {
                float2 r0 = *(const float2*)(dd.res + (size_t)r * N + c);
                float2 r1 = *(const float2*)(dd.res + (size_t)(r + 8) * N + c);
                v0 += r0.x; v1 += r0.y; v2 += r1.x; v3 += r1.y;
            }
            *(float2*)(dd.C + (size_t)r * N + c) = make_float2(v0, v1);
            *(float2*)(dd.C + (size_t)(r + 8) * N + c) = make_float2(v2, v3);
        }
    }
}

#define SMEM_A (2 * 2 * (64 * 80 + 128 * 80))   // <64,128>: 61440
#define SMEM_B (2 * 2 * (64 * 80 + 64 * 80))    // <64,64>:  40960
#define SMEM_C (2 * 2 * (128 * 80 + 64 * 80))   // <128,64>: 61440

// ================= combine: C = p0 + p1 + bias + res (Wd only) =============
__global__ __launch_bounds__(256) void combine_kernel(
        const float* __restrict__ p0, const float* __restrict__ p1,
        const float* __restrict__ bias, const float* __restrict__ res,
        float* __restrict__ C) {
    int i = blockIdx.x * 256 + threadIdx.x;      // float4 index, N = 1024
    float4 x = ((const float4*)p0)[i];
    float4 y = ((const float4*)p1)[i];
    float4 b = ((const float4*)bias)[i & 255];
    float4 r = ((const float4*)res)[i];
    ((float4*)C)[i] = make_float4(x.x + y.x + b.x + r.x, x.y + y.y + b.y + r.y,
                                  x.z + y.z + b.z + r.z, x.w + y.w + b.w + r.w);
}

// ================= fused causal conv (k=4) + silu + i/f gates ================
__global__ __launch_bounds__(256) void conv_if_kernel(
        const float* __restrict__ xt, const float* __restrict__ w,
        const float* __restrict__ cb, float* __restrict__ xc,
        const float* __restrict__ Wi, const float* __restrict__ bi,
        const float* __restrict__ Wf, const float* __restrict__ bfb,
        const float* __restrict__ m_tm1, float* __restrict__ m_out,
        float* __restrict__ ie, float* __restrict__ fe) {
    __shared__ float sx[P];
    __shared__ float sc[P];
    int b = blockIdx.x;
    int tid = threadIdx.x;
    const float4* xr = (const float4*)(xt + (size_t)b * P);
    #pragma unroll
    for (int i = 0; i < P / 4 / 256; i++)
        ((float4*)sx)[tid + i * 256] = xr[tid + i * 256];
    float w0 = w[0], w1 = w[1], w2 = w[2], w3 = w[3], cbv = cb[0];
    __syncthreads();
    #pragma unroll
    for (int i = 0; i < P / 256; i++) {
        int p = tid + i * 256;
        float acc = cbv + w3 * sx[p];
        if (p >= 1) acc += w2 * sx[p - 1];
        if (p >= 2) acc += w1 * sx[p - 2];
        if (p >= 3) acc += w0 * sx[p - 3];
        float s = acc / (1.f + expf(-acc));
        sc[p] = s;
        xc[(size_t)b * P + p] = s;
    }
    __syncthreads();
    int h = tid >> 5, lane = tid & 31;
    const float* wi = Wi + (size_t)h * P;
    const float* wf = Wf + (size_t)h * P;
    float ai = 0.f, af = 0.f;
    #pragma unroll
    for (int k = lane * 4; k < P; k += 128) {
        float4 xv  = *(const float4*)(sc + k);
        float4 wiv = *(const float4*)(wi + k);
        float4 wfv = *(const float4*)(wf + k);
        ai += xv.x * wiv.x + xv.y * wiv.y + xv.z * wiv.z + xv.w * wiv.w;
        af += xv.x * wfv.x + xv.y * wfv.y + xv.z * wfv.z + xv.w * wfv.w;
    }
    #pragma unroll
    for (int o = 16; o; o >>= 1) {
        ai += __shfl_down_sync(0xffffffffu, ai, o);
        af += __shfl_down_sync(0xffffffffu, af, o);
    }
    if (lane == 0) {
        int bh = b * H + h;
        float i_t = ai + bi[h];
        float f_t = af + bfb[h];
        float mp = m_tm1[bh];
        float m = fmaxf(f_t + mp, i_t);
        m_out[bh] = m;
        ie[bh] = expf(i_t - m);
        fe[bh] = expf(f_t - m + mp);
    }
}

// ================= fused combine + state update + readout + groupnorm =======
__global__ __launch_bounds__(128) void state_kernel(
    const float* __restrict__ c_tm1, const float* __restrict__ n_tm1,
    const float* __restrict__ p0, const float* __restrict__ p1,
    const float* __restrict__ bq, const float* __restrict__ bk,
    const float* __restrict__ bv, const float* __restrict__ bo,
    const float* __restrict__ ie_, const float* __restrict__ fe_,
    const float* __restrict__ r,
    const float* __restrict__ gn_g, const float* __restrict__ gn_b,
    float* __restrict__ c_out, float* __restrict__ n_out, float* __restrict__ y) {
    int bh = blockIdx.x;
    int b = bh >> 3, h = bh & 7;
    __shared__ float qs[D], ks[D], vs[D], hnum[D];
    __shared__ float red[4], rs1[4], rs2[4];
    int tid = threadIdx.x;
    int base = b * HD + h * D;
    int hb = h * D + tid;
    qs[tid] = p0[0 * SEG + base + tid] + p1[0 * SEG + base + tid] + bq[hb];
    ks[tid] = (p0[1 * SEG + base + tid] + p1[1 * SEG + base + tid] + bk[hb])
              * 0.08838834764831845f;   // 1/sqrt(128)
    vs[tid] = p0[2 * SEG + base + tid] + p1[2 * SEG + base + tid] + bv[hb];
    float ov = p0[3 * SEG + base + tid] + p1[3 * SEG + base + tid] + bo[hb];
    ov = 1.f / (1.f + expf(-ov));
    float skv = p0[4 * SEG + base + tid] + p1[4 * SEG + base + tid];
    float ie = ie_[bh], fe = fe_[bh];
    __syncthreads();

    const float4* crow = (const float4*)(c_tm1 + (size_t)bh * D * D);
    float4* cout = (float4*)(c_out + (size_t)bh * D * D);
    int w = tid >> 5, lane = tid & 31;
    float4 k4 = ((const float4*)ks)[lane];
    float4 q4 = ((const float4*)qs)[lane];
    #pragma unroll 4
    for (int it = 0; it < 32; it++) {
        int d = it * 4 + w;
        float4 c4 = crow[d * 32 + lane];
        float ivd = ie * vs[d];
        float4 cn;
        cn.x = fe * c4.x + ivd * k4.x;
        cn.y = fe * c4.y + ivd * k4.y;
        cn.z = fe * c4.z + ivd * k4.z;
        cn.w = fe * c4.w + ivd * k4.w;
        cout[d * 32 + lane] = cn;
        float part = cn.x * q4.x + cn.y * q4.y + cn.z * q4.z + cn.w * q4.w;
        #pragma unroll
        for (int off = 16; off; off >>= 1) part += __shfl_down_sync(0xffffffffu, part, off);
        if (lane == 0) hnum[d] = part;
    }
    __syncthreads();

    int d = tid;
    float nv = fe * n_tm1[bh * D + d] + ie * ks[d];
    n_out[bh * D + d] = nv;
    float dn = nv * qs[d];
    #pragma unroll
    for (int off = 16; off; off >>= 1) dn += __shfl_down_sync(0xffffffffu, dn, off);
    if (lane == 0) red[w] = dn;
    __syncthreads();
    float denom = fmaxf(red[0] + red[1] + red[2] + red[3], 1.0f);
    float ht = ov * hnum[d] / denom;

    float s1 = ht, s2 = ht * ht;
    #pragma unroll
    for (int off = 16; off; off >>= 1) {
        s1 += __shfl_down_sync(0xffffffffu, s1, off);
        s2 += __shfl_down_sync(0xffffffffu, s2, off);
    }
    if (lane == 0) { rs1[w] = s1; rs2[w] = s2; }
    __syncthreads();
    float mu  = (rs1[0] + rs1[1] + rs1[2] + rs1[3]) * (1.f / D);
    float var = (rs2[0] + rs2[1] + rs2[2] + rs2[3]) * (1.f / D) - mu * mu;
    float rstd = rsqrtf(var + 1e-5f);
    float xn = (ht - mu) * rstd * gn_g[hb] + gn_b[hb];
    float rv = r[base + d];
    float yv = (xn + skv) * (rv / (1.f + expf(-rv)));
    y[base + d] = yv;
}

// ---------------------------------------------------------------------------
extern "C" void kernel_launch(void* const* d_in, const int* in_sizes, int n_in,
                              void* d_out, int out_size) {
    const float* seq    = (const float*)d_in[0];
    const float* c_tm1  = (const float*)d_in[1];
    const float* n_tm1  = (const float*)d_in[2];
    const float* m_tm1  = (const float*)d_in[3];
    const float* ln_g   = (const float*)d_in[4];
    const float* ln_b   = (const float*)d_in[5];
    const float* Wul    = (const float*)d_in[6];
    const float* bul    = (const float*)d_in[7];
    const float* Wur    = (const float*)d_in[8];
    const float* bur    = (const float*)d_in[9];
    const float* conv_w = (const float*)d_in[10];
    const float* conv_b = (const float*)d_in[11];
    const float* Wskip  = (const float*)d_in[12];
    const float* Wi     = (const float*)d_in[13];
    const float* bi     = (const float*)d_in[14];
    const float* Wf     = (const float*)d_in[15];
    const float* bf     = (const float*)d_in[16];
    const float* Wo     = (const float*)d_in[17];
    const float* bo     = (const float*)d_in[18];
    const float* Wq     = (const float*)d_in[19];
    const float* bq     = (const float*)d_in[20];
    const float* Wk     = (const float*)d_in[21];
    const float* bk     = (const float*)d_in[22];
    const float* Wv     = (const float*)d_in[23];
    const float* bv     = (const float*)d_in[24];
    const float* gn_g   = (const float*)d_in[25];
    const float* gn_b   = (const float*)d_in[26];
    const float* Wd     = (const float*)d_in[27];
    const float* bd     = (const float*)d_in[28];

    float* out   = (float*)d_out;
    float* c_out = out + (size_t)B * DIM;
    float* n_out = c_out + (size_t)B * H * D * D;
    float* m_out = n_out + (size_t)B * H * D;

    float *xn, *xt, *xc, *rt, *iee, *fee, *yy, *p0, *p1;
    cudaGetSymbolAddress((void**)&xn,  g_xn);
    cudaGetSymbolAddress((void**)&xt,  g_xt);
    cudaGetSymbolAddress((void**)&xc,  g_xc);
    cudaGetSymbolAddress((void**)&rt,  g_rt);
    cudaGetSymbolAddress((void**)&iee, g_ie);
    cudaGetSymbolAddress((void**)&fee, g_fe);
    cudaGetSymbolAddress((void**)&yy,  g_y);
    cudaGetSymbolAddress((void**)&p0,  g_p0);
    cudaGetSymbolAddress((void**)&p1,  g_p1);

    cudaFuncSetAttribute(gemm_mma<64, 128, 256>,
                         cudaFuncAttributeMaxDynamicSharedMemorySize, SMEM_A);
    cudaFuncSetAttribute(gemm_mma<64, 64, 128>,
                         cudaFuncAttributeMaxDynamicSharedMemorySize, SMEM_B);
    cudaFuncSetAttribute(gemm_mma<128, 64, 256>,
                         cudaFuncAttributeMaxDynamicSharedMemorySize, SMEM_C);

    // 1. layernorm
    ln_kernel<<<B, 256>>>(seq, ln_g, ln_b, xn);

    // 2+3. x_t = xn@Wul^T+bul [B,P] and r_t = xn@Wur^T+bur [B,HD]
    {
        GemmArgs a{};
        a.d[0] = {xn, Wul, bul, nullptr, xt, P,  DIM, DIM / 32, 0};
        a.d[1] = {xn, Wur, bur, nullptr, rt, HD, DIM, DIM / 32, 0};
        gemm_mma<64, 128, 256><<<dim3(P / 128, B / 64, 2), 256, SMEM_A>>>(a);
    }

    // 4+5. fused causal conv + silu + i/f gates
    conv_if_kernel<<<B, 256>>>(xt, conv_w, conv_b, xc,
                               Wi, bi, Wf, bf, m_tm1, m_out, iee, fee);

    // 6. batched 5x GEMM (N=1024, K=2048) K-split x2, 128x64 tiles, 256 thr
    //    -> 320 CTAs x 8 warps, 2 CTA/SM, 32x32 warp tiles
    {
        const float* As[5] = {xc, xc, xt, xt, xc};
        const float* Ws[5] = {Wq, Wk, Wv, Wo, Wskip};
        GemmArgs a{};
        for (int i = 0; i < 5; i++) {
            a.d[i]     = {As[i],        Ws[i],        nullptr, nullptr,
                          p0 + (size_t)i * SEG, HD, P, 32, 0};
            a.d[i + 5] = {As[i] + 1024, Ws[i] + 1024, nullptr, nullptr,
                          p1 + (size_t)i * SEG, HD, P, 32, 0};
        }
        gemm_mma<128, 64, 256><<<dim3(HD / 64, B / 128, 10), 256, SMEM_C>>>(a);
    }

    // 7. fused combine + state update + readout + groupnorm + skip + gate
    state_kernel<<<B * H, 128>>>(c_tm1, n_tm1, p0, p1, bq, bk, bv, bo,
                                 iee, fee, rt, gn_g, gn_b, c_out, n_out, yy);

    // 8. out = y @ Wd^T + bd + seq : K-split x2 -> 128 CTAs + combine
    {
        GemmArgs a{};
        a.d[0] = {yy,       Wd,       nullptr, nullptr, p0 + 5 * SEG, DIM, HD, 16, 0};
        a.d[1] = {yy + 512, Wd + 512, nullptr, nullptr, p1 + 5 * SEG, DIM, HD, 16, 0};
        gemm_mma<64, 64, 128><<<dim3(DIM / 64, B / 64, 2), 128, SMEM_B>>>(a);
    }
    combine_kernel<<<SEG / 4 / 256, 256>>>(p0 + 5 * SEG, p1 + 5 * SEG, bd, seq, out);
}